// round 8
// baseline (speedup 1.0000x reference)
#include <cuda_runtime.h>
#include <cstdint>

// ---------------------------------------------------------------------------
// ViT patch-embed + QKV + attention (round 7 = round 6 + Vs stride fix)
//  - GEMMs: tf32 mma 3x-split (round 5, v scatter -> g_vn[n][48])
//  - attention: tf32 mma 3x-split for QK^T and PV, smem K/P union
//  - FIX vs R6: Vs smem tile stride 40 -> 56 (R6 overflowed Vs and truncated
//    dims 40..47; stride 56 is also conflict-free: banks {g,g+8,g+16,g+24})
// ---------------------------------------------------------------------------

namespace {
constexpr int B_    = 8;
constexpr int NTOK  = 1024;
constexpr int CDIM  = 588;
constexpr int NH    = 14;
constexpr int HD    = 42;
constexpr int MTOT  = B_ * NTOK;     // 8192
constexpr int QKVN  = 3 * CDIM;      // 1764
constexpr float ATTN_SCALE = 0.125f;
constexpr int VSTR  = 56;            // Vs smem stride
}

__device__ float g_patches[MTOT * CDIM];
__device__ float g_tokens [MTOT * CDIM];
__device__ float g_qT[B_ * NH * HD * NTOK];
__device__ float g_kT[B_ * NH * HD * NTOK];
__device__ float g_vn[B_ * NH * NTOK * 48];   // [bh][n][48] (d padded to 48)

// ---------------------------------------------------------------------------
__global__ __launch_bounds__(256) void patch_extract_k(const float* __restrict__ x) {
    int idx = blockIdx.x * 256 + threadIdx.x;
    if (idx >= MTOT * CDIM) return;
    int m = idx / CDIM;
    int k = idx - m * CDIM;
    int c  = k / 196;
    int r2 = k - c * 196;
    int i  = r2 / 14;
    int j  = r2 - i * 14;
    int b  = m >> 10;
    int sp = m & 1023;
    int py = sp >> 5;
    int px = sp & 31;
    g_patches[idx] = x[((size_t)(b * 3 + c) * 448 + py * 14 + i) * 448 + (px * 14 + j)];
}

// ---------------------------------------------------------------------------
// tf32 helpers (layouts validated by round-5 GEMM pass)
// ---------------------------------------------------------------------------
__device__ __forceinline__ void split_tf32(float x, uint32_t& hi, uint32_t& lo) {
    asm("cvt.rna.tf32.f32 %0, %1;" : "=r"(hi) : "f"(x));
    float r = x - __uint_as_float(hi);
    asm("cvt.rna.tf32.f32 %0, %1;" : "=r"(lo) : "f"(r));
}

__device__ __forceinline__ void mma_tf32(float* d, const uint32_t* a, const uint32_t* b) {
    asm volatile(
        "mma.sync.aligned.m16n8k8.row.col.f32.tf32.tf32.f32 "
        "{%0,%1,%2,%3}, {%4,%5,%6,%7}, {%8,%9}, {%0,%1,%2,%3};"
        : "+f"(d[0]), "+f"(d[1]), "+f"(d[2]), "+f"(d[3])
        : "r"(a[0]), "r"(a[1]), "r"(a[2]), "r"(a[3]), "r"(b[0]), "r"(b[1]));
}

// ---------------------------------------------------------------------------
// Tensor-core GEMM: C[M,NCOLS] = A[M,588] @ W[NCOLS,588]^T + bias
// ---------------------------------------------------------------------------
template<int NCOLS, bool SCATTER>
__global__ __launch_bounds__(256) void gemm_mma_k(const float* __restrict__ W,
                                                  const float* __restrict__ bias) {
    constexpr int K  = CDIM;
    constexpr int BK = 16;
    __shared__ float As[BK][136];
    __shared__ float Bs[BK][72];

    const float* __restrict__ A = SCATTER ? g_tokens : g_patches;

    int tid  = threadIdx.x;
    int lane = tid & 31;
    int wid  = tid >> 5;
    int g = lane >> 2, t = lane & 3;
    int wm0 = (wid >> 1) << 5;
    int wn0 = (wid & 1) << 5;
    int m0 = blockIdx.y << 7, n0 = blockIdx.x << 6;

    int l_row = tid >> 2;
    int l_kq  = (tid & 3) << 2;

    float acc[2][4][4] = {};

    for (int k0 = 0; k0 < K; k0 += BK) {
        bool kok = (k0 + l_kq) < K;
        #pragma unroll
        for (int h = 0; h < 2; h++) {
            int m = l_row + h * 64;
            float4 v = make_float4(0.f, 0.f, 0.f, 0.f);
            if (kok) v = *(const float4*)&A[(size_t)(m0 + m) * K + k0 + l_kq];
            As[l_kq + 0][m] = v.x; As[l_kq + 1][m] = v.y;
            As[l_kq + 2][m] = v.z; As[l_kq + 3][m] = v.w;
        }
        {
            float4 v = make_float4(0.f, 0.f, 0.f, 0.f);
            if (kok && (n0 + l_row) < NCOLS)
                v = *(const float4*)&W[(size_t)(n0 + l_row) * K + k0 + l_kq];
            Bs[l_kq + 0][l_row] = v.x; Bs[l_kq + 1][l_row] = v.y;
            Bs[l_kq + 2][l_row] = v.z; Bs[l_kq + 3][l_row] = v.w;
        }
        __syncthreads();

        #pragma unroll
        for (int ks = 0; ks < 2; ks++) {
            int kb = ks << 3;
            uint32_t ahi[2][4], alo[2][4], bhi[4][2], blo[4][2];
            #pragma unroll
            for (int mi = 0; mi < 2; mi++) {
                int mb = wm0 + 16 * mi + g;
                split_tf32(As[kb + t    ][mb    ], ahi[mi][0], alo[mi][0]);
                split_tf32(As[kb + t    ][mb + 8], ahi[mi][1], alo[mi][1]);
                split_tf32(As[kb + t + 4][mb    ], ahi[mi][2], alo[mi][2]);
                split_tf32(As[kb + t + 4][mb + 8], ahi[mi][3], alo[mi][3]);
            }
            #pragma unroll
            for (int ni = 0; ni < 4; ni++) {
                int nb = wn0 + 8 * ni + g;
                split_tf32(Bs[kb + t    ][nb], bhi[ni][0], blo[ni][0]);
                split_tf32(Bs[kb + t + 4][nb], bhi[ni][1], blo[ni][1]);
            }
            #pragma unroll
            for (int mi = 0; mi < 2; mi++)
                #pragma unroll
                for (int ni = 0; ni < 4; ni++) {
                    mma_tf32(acc[mi][ni], alo[mi], bhi[ni]);
                    mma_tf32(acc[mi][ni], ahi[mi], blo[ni]);
                    mma_tf32(acc[mi][ni], ahi[mi], bhi[ni]);
                }
        }
        __syncthreads();
    }

    #pragma unroll
    for (int mi = 0; mi < 2; mi++) {
        #pragma unroll
        for (int ci = 0; ci < 4; ci++) {
            int m = m0 + wm0 + 16 * mi + g + ((ci >= 2) ? 8 : 0);
            int b = m >> 10, n = m & 1023;
            #pragma unroll
            for (int ni = 0; ni < 4; ni++) {
                int o = n0 + wn0 + 8 * ni + 2 * t + (ci & 1);
                if (o < NCOLS) {
                    float val = acc[mi][ni][ci] + bias[o];
                    if (!SCATTER) {
                        g_tokens[(size_t)m * NCOLS + o] = val;
                    } else {
                        int sgrp = o / CDIM;
                        int cc   = o - sgrp * CDIM;
                        int h    = cc / HD;
                        int d    = cc - h * HD;
                        int bh   = b * NH + h;
                        if (sgrp == 0)
                            g_qT[((size_t)bh * HD + d) * NTOK + n] = val;
                        else if (sgrp == 1)
                            g_kT[((size_t)bh * HD + d) * NTOK + n] = val;
                        else
                            g_vn[((size_t)bh * NTOK + n) * 48 + d] = val;
                    }
                }
            }
        }
    }
}

// ---------------------------------------------------------------------------
// Tensor-core flash attention per (b,h). BR=64 rows/CTA, 16 KV tiles of 64.
// 8 warps: warp w -> rows 16*(w&3); half (w>>2) of cols (QK) / dims (PV).
// smem: Qs[48][72] (k x m), KsPs union: Ks[48][72] (k x n) then Ps[64][68],
//       Vs[64][VSTR] (k x n). Fragment-load patterns conflict-free.
// ---------------------------------------------------------------------------
__global__ __launch_bounds__(256) void attn_k(float* __restrict__ out) {
    __shared__ float Qs[48 * 72];
    __shared__ float KsPs[64 * 68];   // Ks needs 48*72=3456 <= 4352
    __shared__ float Vs[64 * VSTR];
    __shared__ float smax[2][64];
    __shared__ float ssum[2][64];

    int tid  = threadIdx.x;
    int lane = tid & 31, w = tid >> 5;
    int g = lane >> 2, t = lane & 3;
    int wm    = (w & 3) << 4;      // row block base: 0,16,32,48
    int whalf = w >> 2;            // 0/1
    int ncol0 = whalf << 5;        // QK col half base
    int dcol0 = whalf * 24;        // PV dim half base
    int bh = blockIdx.y;
    int r0 = blockIdx.x << 6;

    const float* qb = g_qT + (size_t)bh * HD * NTOK + r0;
    const float* kp = g_kT + (size_t)bh * HD * NTOK;
    const float* vb = g_vn + (size_t)bh * NTOK * 48;

    for (int idx = tid; idx < 48 * 64; idx += 256) {
        int d = idx >> 6, r = idx & 63;
        Qs[d * 72 + r] = (d < HD) ? qb[(size_t)d * NTOK + r] : 0.f;
    }

    float m0r = -1e30f, m1r = -1e30f, l0r = 0.f, l1r = 0.f;
    float o[3][4] = {};

    for (int c0 = 0; c0 < NTOK; c0 += 64) {
        // K tile (zero-pad rows 42..47 every tile: P clobbers the region)
        for (int idx = tid; idx < 48 * 64; idx += 256) {
            int d = idx >> 6, c = idx & 63;
            KsPs[d * 72 + c] = (d < HD) ? kp[(size_t)d * NTOK + c0 + c] : 0.f;
        }
        // V tile [c][d], stride VSTR, pad d>=HD with 0
        for (int idx = tid; idx < 64 * VSTR; idx += 256) {
            int c = idx / VSTR, d = idx - c * VSTR;
            Vs[idx] = (d < HD) ? vb[(size_t)(c0 + c) * 48 + d] : 0.f;
        }
        __syncthreads();

        // --- S = Q K^T ---
        float s[4][4] = {};
        #pragma unroll
        for (int kk = 0; kk < 6; kk++) {
            int kb8 = kk << 3;
            uint32_t ahi[4], alo[4];
            split_tf32(Qs[(kb8 + t) * 72 + wm + g],         ahi[0], alo[0]);
            split_tf32(Qs[(kb8 + t) * 72 + wm + 8 + g],     ahi[1], alo[1]);
            split_tf32(Qs[(kb8 + t + 4) * 72 + wm + g],     ahi[2], alo[2]);
            split_tf32(Qs[(kb8 + t + 4) * 72 + wm + 8 + g], ahi[3], alo[3]);
            #pragma unroll
            for (int nb = 0; nb < 4; nb++) {
                int nc = ncol0 + (nb << 3) + g;
                uint32_t bhi[2], blo[2];
                split_tf32(KsPs[(kb8 + t) * 72 + nc],     bhi[0], blo[0]);
                split_tf32(KsPs[(kb8 + t + 4) * 72 + nc], bhi[1], blo[1]);
                mma_tf32(s[nb], alo, bhi);
                mma_tf32(s[nb], ahi, blo);
                mma_tf32(s[nb], ahi, bhi);
            }
        }

        // --- online softmax (row stats split across the 2 col-half warps) ---
        float pm0 = -1e30f, pm1 = -1e30f;
        #pragma unroll
        for (int nb = 0; nb < 4; nb++) {
            s[nb][0] *= ATTN_SCALE; s[nb][1] *= ATTN_SCALE;
            s[nb][2] *= ATTN_SCALE; s[nb][3] *= ATTN_SCALE;
            pm0 = fmaxf(pm0, fmaxf(s[nb][0], s[nb][1]));
            pm1 = fmaxf(pm1, fmaxf(s[nb][2], s[nb][3]));
        }
        pm0 = fmaxf(pm0, __shfl_xor_sync(0xffffffffu, pm0, 1));
        pm0 = fmaxf(pm0, __shfl_xor_sync(0xffffffffu, pm0, 2));
        pm1 = fmaxf(pm1, __shfl_xor_sync(0xffffffffu, pm1, 1));
        pm1 = fmaxf(pm1, __shfl_xor_sync(0xffffffffu, pm1, 2));
        if (t == 0) { smax[whalf][wm + g] = pm0; smax[whalf][wm + 8 + g] = pm1; }
        __syncthreads();   // also guarantees all K reads done before P store

        float mn0 = fmaxf(m0r, fmaxf(smax[0][wm + g],     smax[1][wm + g]));
        float mn1 = fmaxf(m1r, fmaxf(smax[0][wm + 8 + g], smax[1][wm + 8 + g]));
        float al0 = __expf(m0r - mn0), al1 = __expf(m1r - mn1);
        m0r = mn0; m1r = mn1;

        float ps0 = 0.f, ps1 = 0.f;
        #pragma unroll
        for (int nb = 0; nb < 4; nb++) {
            s[nb][0] = __expf(s[nb][0] - mn0); s[nb][1] = __expf(s[nb][1] - mn0);
            s[nb][2] = __expf(s[nb][2] - mn1); s[nb][3] = __expf(s[nb][3] - mn1);
            ps0 += s[nb][0] + s[nb][1];
            ps1 += s[nb][2] + s[nb][3];
        }
        ps0 += __shfl_xor_sync(0xffffffffu, ps0, 1);
        ps0 += __shfl_xor_sync(0xffffffffu, ps0, 2);
        ps1 += __shfl_xor_sync(0xffffffffu, ps1, 1);
        ps1 += __shfl_xor_sync(0xffffffffu, ps1, 2);
        if (t == 0) { ssum[whalf][wm + g] = ps0; ssum[whalf][wm + 8 + g] = ps1; }

        // store P into the Ks region
        #pragma unroll
        for (int nb = 0; nb < 4; nb++) {
            int cc = ncol0 + (nb << 3) + (t << 1);
            KsPs[(wm + g) * 68 + cc]         = s[nb][0];
            KsPs[(wm + g) * 68 + cc + 1]     = s[nb][1];
            KsPs[(wm + 8 + g) * 68 + cc]     = s[nb][2];
            KsPs[(wm + 8 + g) * 68 + cc + 1] = s[nb][3];
        }
        __syncthreads();

        l0r = l0r * al0 + ssum[0][wm + g]     + ssum[1][wm + g];
        l1r = l1r * al1 + ssum[0][wm + 8 + g] + ssum[1][wm + 8 + g];
        #pragma unroll
        for (int f = 0; f < 3; f++) {
            o[f][0] *= al0; o[f][1] *= al0; o[f][2] *= al1; o[f][3] *= al1;
        }

        // --- O += P V ---
        #pragma unroll
        for (int kk = 0; kk < 8; kk++) {
            int kb8 = kk << 3;
            uint32_t ahi[4], alo[4];
            split_tf32(KsPs[(wm + g) * 68 + kb8 + t],         ahi[0], alo[0]);
            split_tf32(KsPs[(wm + 8 + g) * 68 + kb8 + t],     ahi[1], alo[1]);
            split_tf32(KsPs[(wm + g) * 68 + kb8 + t + 4],     ahi[2], alo[2]);
            split_tf32(KsPs[(wm + 8 + g) * 68 + kb8 + t + 4], ahi[3], alo[3]);
            #pragma unroll
            for (int nb = 0; nb < 3; nb++) {
                int dc = dcol0 + (nb << 3) + g;
                uint32_t bhi[2], blo[2];
                split_tf32(Vs[(kb8 + t) * VSTR + dc],     bhi[0], blo[0]);
                split_tf32(Vs[(kb8 + t + 4) * VSTR + dc], bhi[1], blo[1]);
                mma_tf32(o[nb], alo, bhi);
                mma_tf32(o[nb], ahi, blo);
                mma_tf32(o[nb], ahi, bhi);
            }
        }
        __syncthreads();   // before next tile overwrites Ks/Ps and Vs
    }

    int b = bh / NH, h = bh - b * NH;
    float inv0 = 1.f / l0r, inv1 = 1.f / l1r;
    size_t row0 = (size_t)(b * NTOK + r0 + wm + g) * CDIM + h * HD;
    size_t row1 = (size_t)(b * NTOK + r0 + wm + 8 + g) * CDIM + h * HD;
    #pragma unroll
    for (int nb = 0; nb < 3; nb++) {
        int d = dcol0 + (nb << 3) + (t << 1);
        if (d < HD)     out[row0 + d]     = o[nb][0] * inv0;
        if (d + 1 < HD) out[row0 + d + 1] = o[nb][1] * inv0;
        if (d < HD)     out[row1 + d]     = o[nb][2] * inv1;
        if (d + 1 < HD) out[row1 + d + 1] = o[nb][3] * inv1;
    }
}

// ---------------------------------------------------------------------------
extern "C" void kernel_launch(void* const* d_in, const int* in_sizes, int n_in,
                              void* d_out, int out_size) {
    const float* x      = (const float*)d_in[0];
    const float* conv_w = (const float*)d_in[1];
    const float* conv_b = (const float*)d_in[2];
    const float* qkv_w  = (const float*)d_in[3];
    const float* qkv_b  = (const float*)d_in[4];
    float* out = (float*)d_out;

    patch_extract_k<<<(MTOT * CDIM + 255) / 256, 256>>>(x);
    gemm_mma_k<CDIM, false><<<dim3((CDIM + 63) / 64, MTOT / 128), 256>>>(conv_w, conv_b);
    gemm_mma_k<QKVN, true ><<<dim3((QKVN + 63) / 64, MTOT / 128), 256>>>(qkv_w, qkv_b);
    attn_k<<<dim3(NTOK / 64, B_ * NH), 256>>>(out);
}

// round 9
// speedup vs baseline: 1.2577x; 1.2577x over previous
#include <cuda_runtime.h>
#include <cstdint>

// ---------------------------------------------------------------------------
// ViT patch-embed + QKV + attention (round 8)
//  - GEMMs: tf32 mma 3x-split (validated R5)
//  - GEMM2 epilogue pre-splits q/k/v into bf16 hi/lo planes (packed pairs)
//  - attention: bf16 mma.m16n8k16 3x-split, zero conversions in hot loop
// ---------------------------------------------------------------------------

namespace {
constexpr int B_    = 8;
constexpr int NTOK  = 1024;
constexpr int CDIM  = 588;
constexpr int NH    = 14;
constexpr int HD    = 42;
constexpr int MTOT  = B_ * NTOK;     // 8192
constexpr int QKVN  = 3 * CDIM;      // 1764
constexpr int BH    = B_ * NH;       // 112
constexpr float ATTN_SCALE = 0.125f;
}

__device__ float g_patches[MTOT * CDIM];
__device__ float g_tokens [MTOT * CDIM];
// q,k: packed d-pair planes [bh][token][24] (pairs 21..23 stay zero-init)
__device__ uint32_t g_qp_hi[BH * NTOK * 24];
__device__ uint32_t g_qp_lo[BH * NTOK * 24];
__device__ uint32_t g_kp_hi[BH * NTOK * 24];
__device__ uint32_t g_kp_lo[BH * NTOK * 24];
// v: scalar bf16 planes [bh][d(48, 42..47 zero)][token]
__device__ uint16_t g_vh16[BH * 48 * NTOK];
__device__ uint16_t g_vl16[BH * 48 * NTOK];

// ---------------------------------------------------------------------------
__global__ __launch_bounds__(256) void patch_extract_k(const float* __restrict__ x) {
    int idx = blockIdx.x * 256 + threadIdx.x;
    if (idx >= MTOT * CDIM) return;
    int m = idx / CDIM;
    int k = idx - m * CDIM;
    int c  = k / 196;
    int r2 = k - c * 196;
    int i  = r2 / 14;
    int j  = r2 - i * 14;
    int b  = m >> 10;
    int sp = m & 1023;
    int py = sp >> 5;
    int px = sp & 31;
    g_patches[idx] = x[((size_t)(b * 3 + c) * 448 + py * 14 + i) * 448 + (px * 14 + j)];
}

// ---------------------------------------------------------------------------
// helpers
// ---------------------------------------------------------------------------
__device__ __forceinline__ void split_tf32(float x, uint32_t& hi, uint32_t& lo) {
    asm("cvt.rna.tf32.f32 %0, %1;" : "=r"(hi) : "f"(x));
    float r = x - __uint_as_float(hi);
    asm("cvt.rna.tf32.f32 %0, %1;" : "=r"(lo) : "f"(r));
}

__device__ __forceinline__ void mma_tf32(float* d, const uint32_t* a, const uint32_t* b) {
    asm volatile(
        "mma.sync.aligned.m16n8k8.row.col.f32.tf32.tf32.f32 "
        "{%0,%1,%2,%3}, {%4,%5,%6,%7}, {%8,%9}, {%0,%1,%2,%3};"
        : "+f"(d[0]), "+f"(d[1]), "+f"(d[2]), "+f"(d[3])
        : "r"(a[0]), "r"(a[1]), "r"(a[2]), "r"(a[3]), "r"(b[0]), "r"(b[1]));
}

__device__ __forceinline__ void mma_bf16(float* d, const uint32_t* a, const uint32_t* b) {
    asm volatile(
        "mma.sync.aligned.m16n8k16.row.col.f32.bf16.bf16.f32 "
        "{%0,%1,%2,%3}, {%4,%5,%6,%7}, {%8,%9}, {%0,%1,%2,%3};"
        : "+f"(d[0]), "+f"(d[1]), "+f"(d[2]), "+f"(d[3])
        : "r"(a[0]), "r"(a[1]), "r"(a[2]), "r"(a[3]), "r"(b[0]), "r"(b[1]));
}

// pack two floats as bf16x2: lo16 = vlo, hi16 = vhi
__device__ __forceinline__ uint32_t pack_bf16x2(float vlo, float vhi) {
    uint32_t r;
    asm("cvt.rn.bf16x2.f32 %0, %1, %2;" : "=r"(r) : "f"(vhi), "f"(vlo));
    return r;
}

// ---------------------------------------------------------------------------
// Tensor-core GEMM: C[M,NCOLS] = A[M,588] @ W[NCOLS,588]^T + bias
// SCATTER=true epilogue writes bf16 hi/lo split planes for q/k/v.
// ---------------------------------------------------------------------------
template<int NCOLS, bool SCATTER>
__global__ __launch_bounds__(256) void gemm_mma_k(const float* __restrict__ W,
                                                  const float* __restrict__ bias) {
    constexpr int K  = CDIM;
    constexpr int BK = 16;
    __shared__ float As[BK][136];
    __shared__ float Bs[BK][72];

    const float* __restrict__ A = SCATTER ? g_tokens : g_patches;

    int tid  = threadIdx.x;
    int lane = tid & 31;
    int wid  = tid >> 5;
    int g = lane >> 2, t = lane & 3;
    int wm0 = (wid >> 1) << 5;
    int wn0 = (wid & 1) << 5;
    int m0 = blockIdx.y << 7, n0 = blockIdx.x << 6;

    int l_row = tid >> 2;
    int l_kq  = (tid & 3) << 2;

    float acc[2][4][4] = {};

    for (int k0 = 0; k0 < K; k0 += BK) {
        bool kok = (k0 + l_kq) < K;
        #pragma unroll
        for (int h = 0; h < 2; h++) {
            int m = l_row + h * 64;
            float4 v = make_float4(0.f, 0.f, 0.f, 0.f);
            if (kok) v = *(const float4*)&A[(size_t)(m0 + m) * K + k0 + l_kq];
            As[l_kq + 0][m] = v.x; As[l_kq + 1][m] = v.y;
            As[l_kq + 2][m] = v.z; As[l_kq + 3][m] = v.w;
        }
        {
            float4 v = make_float4(0.f, 0.f, 0.f, 0.f);
            if (kok && (n0 + l_row) < NCOLS)
                v = *(const float4*)&W[(size_t)(n0 + l_row) * K + k0 + l_kq];
            Bs[l_kq + 0][l_row] = v.x; Bs[l_kq + 1][l_row] = v.y;
            Bs[l_kq + 2][l_row] = v.z; Bs[l_kq + 3][l_row] = v.w;
        }
        __syncthreads();

        #pragma unroll
        for (int ks = 0; ks < 2; ks++) {
            int kb = ks << 3;
            uint32_t ahi[2][4], alo[2][4], bhi[4][2], blo[4][2];
            #pragma unroll
            for (int mi = 0; mi < 2; mi++) {
                int mb = wm0 + 16 * mi + g;
                split_tf32(As[kb + t    ][mb    ], ahi[mi][0], alo[mi][0]);
                split_tf32(As[kb + t    ][mb + 8], ahi[mi][1], alo[mi][1]);
                split_tf32(As[kb + t + 4][mb    ], ahi[mi][2], alo[mi][2]);
                split_tf32(As[kb + t + 4][mb + 8], ahi[mi][3], alo[mi][3]);
            }
            #pragma unroll
            for (int ni = 0; ni < 4; ni++) {
                int nb = wn0 + 8 * ni + g;
                split_tf32(Bs[kb + t    ][nb], bhi[ni][0], blo[ni][0]);
                split_tf32(Bs[kb + t + 4][nb], bhi[ni][1], blo[ni][1]);
            }
            #pragma unroll
            for (int mi = 0; mi < 2; mi++)
                #pragma unroll
                for (int ni = 0; ni < 4; ni++) {
                    mma_tf32(acc[mi][ni], alo[mi], bhi[ni]);
                    mma_tf32(acc[mi][ni], ahi[mi], blo[ni]);
                    mma_tf32(acc[mi][ni], ahi[mi], bhi[ni]);
                }
        }
        __syncthreads();
    }

    if (!SCATTER) {
        #pragma unroll
        for (int mi = 0; mi < 2; mi++)
            #pragma unroll
            for (int ci = 0; ci < 4; ci++) {
                int m = m0 + wm0 + 16 * mi + g + ((ci >= 2) ? 8 : 0);
                #pragma unroll
                for (int ni = 0; ni < 4; ni++) {
                    int o = n0 + wn0 + 8 * ni + 2 * t + (ci & 1);
                    if (o < NCOLS)
                        g_tokens[(size_t)m * NCOLS + o] = acc[mi][ni][ci] + bias[o];
                }
            }
    } else {
        // pairs (o, o+1), o even: same sgrp/head, d even pair (42,588 even)
        #pragma unroll
        for (int mi = 0; mi < 2; mi++)
            #pragma unroll
            for (int rh = 0; rh < 2; rh++) {
                int m = m0 + wm0 + 16 * mi + g + 8 * rh;
                int b = m >> 10, n = m & 1023;
                #pragma unroll
                for (int ni = 0; ni < 4; ni++) {
                    int o = n0 + wn0 + 8 * ni + 2 * t;   // even
                    if (o >= NCOLS) continue;
                    float v0 = acc[mi][ni][rh * 2 + 0] + bias[o];
                    float v1 = acc[mi][ni][rh * 2 + 1] + bias[o + 1];
                    int sgrp = o / CDIM;
                    int cc   = o - sgrp * CDIM;          // even
                    int h    = cc / HD;
                    int d    = cc - h * HD;              // even
                    int bh   = b * NH + h;
                    if (sgrp < 2) {
                        uint32_t hw = pack_bf16x2(v0, v1);
                        float r0 = v0 - __uint_as_float(hw << 16);
                        float r1 = v1 - __uint_as_float(hw & 0xffff0000u);
                        uint32_t lw = pack_bf16x2(r0, r1);
                        size_t base = ((size_t)bh * NTOK + n) * 24 + (d >> 1);
                        if (sgrp == 0) { g_qp_hi[base] = hw; g_qp_lo[base] = lw; }
                        else           { g_kp_hi[base] = hw; g_kp_lo[base] = lw; }
                    } else {
                        #pragma unroll
                        for (int e = 0; e < 2; e++) {
                            float val = e ? v1 : v0;
                            uint16_t hb;
                            asm("cvt.rn.bf16.f32 %0, %1;" : "=h"(hb) : "f"(val));
                            float rv = val - __uint_as_float((uint32_t)hb << 16);
                            uint16_t lb;
                            asm("cvt.rn.bf16.f32 %0, %1;" : "=h"(lb) : "f"(rv));
                            size_t vo = ((size_t)bh * 48 + d + e) * NTOK + n;
                            g_vh16[vo] = hb; g_vl16[vo] = lb;
                        }
                    }
                }
            }
    }
}

// ---------------------------------------------------------------------------
// bf16 tensor-core flash attention per (b,h). BR=64 rows/CTA, 16 tiles of 64.
// Warp w: rows 16*(w&3); col half (QK) / dim half (PV) = w>>2.
// smem (uint32 packed bf16 pairs over the k-dim):
//   Qh/Ql[64 r][28]   (pairs over d, 24 used)
//   KPr: K phase  Kh at 0 [64 n][28], Kl at 1792
//        P phase  Ph at 0 [64 r][36], Pl at 2304   (pairs over col)
//   Vh/Vl[48 d][36]   (pairs over token, 32 used)
// All fragment patterns bank-conflict-free (strides 28 -> -4g+t, 36 -> 4g+t).
// ---------------------------------------------------------------------------
__global__ __launch_bounds__(256) void attn_k(float* __restrict__ out) {
    __shared__ uint32_t Qh[64 * 28];
    __shared__ uint32_t Ql[64 * 28];
    __shared__ uint32_t KPr[4608];
    __shared__ uint32_t Vh[48 * 36];
    __shared__ uint32_t Vl[48 * 36];
    __shared__ float smax[2][64];
    __shared__ float ssum[2][64];

    int tid  = threadIdx.x;
    int lane = tid & 31, w = tid >> 5;
    int g = lane >> 2, t = lane & 3;
    int wm    = (w & 3) << 4;
    int whalf = w >> 2;
    int ncol0 = whalf << 5;
    int dcol0 = whalf * 24;
    int bh = blockIdx.y;
    int r0 = blockIdx.x << 6;

    // Q tile (once)
    for (int idx = tid; idx < 64 * 24; idx += 256) {
        int r = idx / 24, p = idx - r * 24;
        size_t gb = ((size_t)bh * NTOK + r0 + r) * 24 + p;
        Qh[r * 28 + p] = g_qp_hi[gb];
        Ql[r * 28 + p] = g_qp_lo[gb];
    }

    float m0r = -1e30f, m1r = -1e30f, l0r = 0.f, l1r = 0.f;
    float o[3][4] = {};

    for (int c0 = 0; c0 < NTOK; c0 += 64) {
        // K tile
        for (int idx = tid; idx < 64 * 24; idx += 256) {
            int n = idx / 24, p = idx - n * 24;
            size_t gb = ((size_t)bh * NTOK + c0 + n) * 24 + p;
            KPr[n * 28 + p]        = g_kp_hi[gb];
            KPr[1792 + n * 28 + p] = g_kp_lo[gb];
        }
        // V tile: packed token-pair loads straight from bf16 planes
        for (int idx = tid; idx < 48 * 32; idx += 256) {
            int d = idx / 32, p = idx - d * 32;
            size_t gb = ((size_t)bh * 48 + d) * NTOK + c0 + 2 * p;
            Vh[d * 36 + p] = *(const uint32_t*)&g_vh16[gb];
            Vl[d * 36 + p] = *(const uint32_t*)&g_vl16[gb];
        }
        __syncthreads();

        // --- S = Q K^T  (3 k-steps of 16) ---
        float s[4][4] = {};
        #pragma unroll
        for (int kk = 0; kk < 3; kk++) {
            int kp0 = 8 * kk + t, kp1 = kp0 + 4;
            uint32_t aH[4] = { Qh[(wm + g) * 28 + kp0], Qh[(wm + 8 + g) * 28 + kp0],
                               Qh[(wm + g) * 28 + kp1], Qh[(wm + 8 + g) * 28 + kp1] };
            uint32_t aL[4] = { Ql[(wm + g) * 28 + kp0], Ql[(wm + 8 + g) * 28 + kp0],
                               Ql[(wm + g) * 28 + kp1], Ql[(wm + 8 + g) * 28 + kp1] };
            #pragma unroll
            for (int nb = 0; nb < 4; nb++) {
                int n = ncol0 + (nb << 3) + g;
                uint32_t bH[2] = { KPr[n * 28 + kp0], KPr[n * 28 + kp1] };
                uint32_t bL[2] = { KPr[1792 + n * 28 + kp0], KPr[1792 + n * 28 + kp1] };
                mma_bf16(s[nb], aL, bH);
                mma_bf16(s[nb], aH, bL);
                mma_bf16(s[nb], aH, bH);
            }
        }

        // --- online softmax ---
        float pm0 = -1e30f, pm1 = -1e30f;
        #pragma unroll
        for (int nb = 0; nb < 4; nb++) {
            s[nb][0] *= ATTN_SCALE; s[nb][1] *= ATTN_SCALE;
            s[nb][2] *= ATTN_SCALE; s[nb][3] *= ATTN_SCALE;
            pm0 = fmaxf(pm0, fmaxf(s[nb][0], s[nb][1]));
            pm1 = fmaxf(pm1, fmaxf(s[nb][2], s[nb][3]));
        }
        pm0 = fmaxf(pm0, __shfl_xor_sync(0xffffffffu, pm0, 1));
        pm0 = fmaxf(pm0, __shfl_xor_sync(0xffffffffu, pm0, 2));
        pm1 = fmaxf(pm1, __shfl_xor_sync(0xffffffffu, pm1, 1));
        pm1 = fmaxf(pm1, __shfl_xor_sync(0xffffffffu, pm1, 2));
        if (t == 0) { smax[whalf][wm + g] = pm0; smax[whalf][wm + 8 + g] = pm1; }
        __syncthreads();   // K reads done; stats visible

        float mn0 = fmaxf(m0r, fmaxf(smax[0][wm + g],     smax[1][wm + g]));
        float mn1 = fmaxf(m1r, fmaxf(smax[0][wm + 8 + g], smax[1][wm + 8 + g]));
        float al0 = __expf(m0r - mn0), al1 = __expf(m1r - mn1);
        m0r = mn0; m1r = mn1;

        float ps0 = 0.f, ps1 = 0.f;
        #pragma unroll
        for (int nb = 0; nb < 4; nb++) {
            s[nb][0] = __expf(s[nb][0] - mn0); s[nb][1] = __expf(s[nb][1] - mn0);
            s[nb][2] = __expf(s[nb][2] - mn1); s[nb][3] = __expf(s[nb][3] - mn1);
            ps0 += s[nb][0] + s[nb][1];
            ps1 += s[nb][2] + s[nb][3];
        }
        ps0 += __shfl_xor_sync(0xffffffffu, ps0, 1);
        ps0 += __shfl_xor_sync(0xffffffffu, ps0, 2);
        ps1 += __shfl_xor_sync(0xffffffffu, ps1, 1);
        ps1 += __shfl_xor_sync(0xffffffffu, ps1, 2);
        if (t == 0) { ssum[whalf][wm + g] = ps0; ssum[whalf][wm + 8 + g] = ps1; }

        // --- split+pack P into the K region (hi at 0, lo at 2304) ---
        #pragma unroll
        for (int nb = 0; nb < 4; nb++) {
            int pcol = (ncol0 >> 1) + 4 * nb + t;
            uint32_t h0 = pack_bf16x2(s[nb][0], s[nb][1]);
            uint32_t l0 = pack_bf16x2(s[nb][0] - __uint_as_float(h0 << 16),
                                      s[nb][1] - __uint_as_float(h0 & 0xffff0000u));
            KPr[(wm + g) * 36 + pcol]        = h0;
            KPr[2304 + (wm + g) * 36 + pcol] = l0;
            uint32_t h1 = pack_bf16x2(s[nb][2], s[nb][3]);
            uint32_t l1 = pack_bf16x2(s[nb][2] - __uint_as_float(h1 << 16),
                                      s[nb][3] - __uint_as_float(h1 & 0xffff0000u));
            KPr[(wm + 8 + g) * 36 + pcol]        = h1;
            KPr[2304 + (wm + 8 + g) * 36 + pcol] = l1;
        }
        __syncthreads();

        l0r = l0r * al0 + ssum[0][wm + g]     + ssum[1][wm + g];
        l1r = l1r * al1 + ssum[0][wm + 8 + g] + ssum[1][wm + 8 + g];
        #pragma unroll
        for (int f = 0; f < 3; f++) {
            o[f][0] *= al0; o[f][1] *= al0; o[f][2] *= al1; o[f][3] *= al1;
        }

        // --- O += P V  (4 k-steps of 16) ---
        #pragma unroll
        for (int kk = 0; kk < 4; kk++) {
            int kp0 = 8 * kk + t, kp1 = kp0 + 4;
            uint32_t aH[4] = { KPr[(wm + g) * 36 + kp0], KPr[(wm + 8 + g) * 36 + kp0],
                               KPr[(wm + g) * 36 + kp1], KPr[(wm + 8 + g) * 36 + kp1] };
            uint32_t aL[4] = { KPr[2304 + (wm + g) * 36 + kp0], KPr[2304 + (wm + 8 + g) * 36 + kp0],
                               KPr[2304 + (wm + g) * 36 + kp1], KPr[2304 + (wm + 8 + g) * 36 + kp1] };
            #pragma unroll
            for (int nb = 0; nb < 3; nb++) {
                int dd = dcol0 + (nb << 3) + g;
                uint32_t bH[2] = { Vh[dd * 36 + kp0], Vh[dd * 36 + kp1] };
                uint32_t bL[2] = { Vl[dd * 36 + kp0], Vl[dd * 36 + kp1] };
                mma_bf16(o[nb], aL, bH);
                mma_bf16(o[nb], aH, bL);
                mma_bf16(o[nb], aH, bH);
            }
        }
        __syncthreads();   // before next tile overwrites K/P and V
    }

    int b = bh / NH, h = bh - b * NH;
    float inv0 = 1.f / l0r, inv1 = 1.f / l1r;
    size_t row0 = (size_t)(b * NTOK + r0 + wm + g) * CDIM + h * HD;
    size_t row1 = (size_t)(b * NTOK + r0 + wm + 8 + g) * CDIM + h * HD;
    #pragma unroll
    for (int nb = 0; nb < 3; nb++) {
        int d = dcol0 + (nb << 3) + (t << 1);
        if (d < HD)     out[row0 + d]     = o[nb][0] * inv0;
        if (d + 1 < HD) out[row0 + d + 1] = o[nb][1] * inv0;
        if (d < HD)     out[row1 + d]     = o[nb][2] * inv1;
        if (d + 1 < HD) out[row1 + d + 1] = o[nb][3] * inv1;
    }
}

// ---------------------------------------------------------------------------
extern "C" void kernel_launch(void* const* d_in, const int* in_sizes, int n_in,
                              void* d_out, int out_size) {
    const float* x      = (const float*)d_in[0];
    const float* conv_w = (const float*)d_in[1];
    const float* conv_b = (const float*)d_in[2];
    const float* qkv_w  = (const float*)d_in[3];
    const float* qkv_b  = (const float*)d_in[4];
    float* out = (float*)d_out;

    patch_extract_k<<<(MTOT * CDIM + 255) / 256, 256>>>(x);
    gemm_mma_k<CDIM, false><<<dim3((CDIM + 63) / 64, MTOT / 128), 256>>>(conv_w, conv_b);
    gemm_mma_k<QKVN, true ><<<dim3((QKVN + 63) / 64, MTOT / 128), 256>>>(qkv_w, qkv_b);
    attn_k<<<dim3(NTOK / 64, B_ * NH), 256>>>(out);
}

// round 10
// speedup vs baseline: 1.5473x; 1.2303x over previous
#include <cuda_runtime.h>
#include <cstdint>

// ---------------------------------------------------------------------------
// ViT patch-embed + QKV + attention (round 9)
//  - ALL matmuls now bf16 m16n8k16 3x-split with pre-split packed operands
//  - patches/weights split once; GEMM1 epilogue emits pre-split tokens
//  - attention: unchanged from round 8 (validated)
// ---------------------------------------------------------------------------

namespace {
constexpr int B_    = 8;
constexpr int NTOK  = 1024;
constexpr int CDIM  = 588;
constexpr int NH    = 14;
constexpr int HD    = 42;
constexpr int MTOT  = B_ * NTOK;     // 8192
constexpr int QKVN  = 3 * CDIM;      // 1764
constexpr int BH    = B_ * NH;       // 112
constexpr float ATTN_SCALE = 0.125f;
constexpr int PAIRS = 304;           // k-pairs per row, K padded 588 -> 608
constexpr int NPAD1 = 640;           // conv_w rows padded
constexpr int NPAD2 = 1792;          // qkv_w rows padded
}

// packed bf16 hi/lo planes (k-pair packed in uint32)
__device__ uint32_t g_pa_hi[MTOT * PAIRS];  // patches
__device__ uint32_t g_pa_lo[MTOT * PAIRS];
__device__ uint32_t g_ta_hi[MTOT * PAIRS];  // tokens
__device__ uint32_t g_ta_lo[MTOT * PAIRS];
__device__ uint32_t g_wc_hi[NPAD1 * PAIRS]; // conv_w
__device__ uint32_t g_wc_lo[NPAD1 * PAIRS];
__device__ uint32_t g_wq_hi[NPAD2 * PAIRS]; // qkv_w
__device__ uint32_t g_wq_lo[NPAD2 * PAIRS];
// attention operands (round-8 layouts)
__device__ uint32_t g_qp_hi[BH * NTOK * 24];
__device__ uint32_t g_qp_lo[BH * NTOK * 24];
__device__ uint32_t g_kp_hi[BH * NTOK * 24];
__device__ uint32_t g_kp_lo[BH * NTOK * 24];
__device__ uint16_t g_vh16[BH * 48 * NTOK];
__device__ uint16_t g_vl16[BH * 48 * NTOK];

// ---------------------------------------------------------------------------
// helpers
// ---------------------------------------------------------------------------
__device__ __forceinline__ uint32_t pack_bf16x2(float vlo, float vhi) {
    uint32_t r;
    asm("cvt.rn.bf16x2.f32 %0, %1, %2;" : "=r"(r) : "f"(vhi), "f"(vlo));
    return r;
}
__device__ __forceinline__ void split_pair(float v0, float v1,
                                           uint32_t& hw, uint32_t& lw) {
    hw = pack_bf16x2(v0, v1);
    float r0 = v0 - __uint_as_float(hw << 16);
    float r1 = v1 - __uint_as_float(hw & 0xffff0000u);
    lw = pack_bf16x2(r0, r1);
}
__device__ __forceinline__ void mma_bf16(float* d, const uint32_t* a, const uint32_t* b) {
    asm volatile(
        "mma.sync.aligned.m16n8k16.row.col.f32.bf16.bf16.f32 "
        "{%0,%1,%2,%3}, {%4,%5,%6,%7}, {%8,%9}, {%0,%1,%2,%3};"
        : "+f"(d[0]), "+f"(d[1]), "+f"(d[2]), "+f"(d[3])
        : "r"(a[0]), "r"(a[1]), "r"(a[2]), "r"(a[3]), "r"(b[0]), "r"(b[1]));
}

// ---------------------------------------------------------------------------
// Patchify + split: g_pa planes[m][p], p = k-pair (k = c*196 + i*14 + j)
// ---------------------------------------------------------------------------
__global__ __launch_bounds__(256) void patch_split_k(const float* __restrict__ x) {
    int idx = blockIdx.x * 256 + threadIdx.x;
    if (idx >= MTOT * 294) return;
    int m = idx / 294;
    int p = idx - m * 294;
    int b  = m >> 10;
    int sp = m & 1023;
    int py = sp >> 5;
    int px = sp & 31;
    float v[2];
    #pragma unroll
    for (int e = 0; e < 2; e++) {
        int k = 2 * p + e;
        int c  = k / 196;
        int r2 = k - c * 196;
        int i  = r2 / 14;
        int j  = r2 - i * 14;
        v[e] = x[((size_t)(b * 3 + c) * 448 + py * 14 + i) * 448 + (px * 14 + j)];
    }
    uint32_t hw, lw;
    split_pair(v[0], v[1], hw, lw);
    g_pa_hi[(size_t)m * PAIRS + p] = hw;
    g_pa_lo[(size_t)m * PAIRS + p] = lw;
}

// ---------------------------------------------------------------------------
// Weight split: rows x 588 fp32 -> packed planes (which: 0=conv, 1=qkv)
// ---------------------------------------------------------------------------
__global__ __launch_bounds__(256) void weight_split_k(const float* __restrict__ W,
                                                      int rows, int which) {
    int idx = blockIdx.x * 256 + threadIdx.x;
    if (idx >= rows * 294) return;
    int r = idx / 294;
    int p = idx - r * 294;
    float v0 = W[(size_t)r * CDIM + 2 * p];
    float v1 = W[(size_t)r * CDIM + 2 * p + 1];
    uint32_t hw, lw;
    split_pair(v0, v1, hw, lw);
    size_t o = (size_t)r * PAIRS + p;
    if (which == 0) { g_wc_hi[o] = hw; g_wc_lo[o] = lw; }
    else            { g_wq_hi[o] = hw; g_wq_lo[o] = lw; }
}

// ---------------------------------------------------------------------------
// bf16 GEMM: C[M,NCOLS] = A[M,K] @ W[NCOLS,K]^T + bias (operands pre-split)
// Tile 128(M) x 64(N) x 32(K=16 pairs); 8 warps 4Mx2N, warp tile 32x32.
// smem [row][pair] stride 20 (banks 20g+t all distinct). 19 k-steps, no guards.
// SCATTER=false: A=patch planes -> token planes (epilogue splits pairs).
// SCATTER=true : A=token planes -> q/k packed planes + v bf16 planes.
// ---------------------------------------------------------------------------
template<int NCOLS, bool SCATTER>
__global__ __launch_bounds__(256) void gemm_bf16_k(const float* __restrict__ bias) {
    __shared__ uint32_t Ah[128 * 20];
    __shared__ uint32_t Al[128 * 20];
    __shared__ uint32_t Bh[64 * 20];
    __shared__ uint32_t Bl[64 * 20];

    const uint32_t* __restrict__ Aph = SCATTER ? g_ta_hi : g_pa_hi;
    const uint32_t* __restrict__ Apl = SCATTER ? g_ta_lo : g_pa_lo;
    const uint32_t* __restrict__ Wph = SCATTER ? g_wq_hi : g_wc_hi;
    const uint32_t* __restrict__ Wpl = SCATTER ? g_wq_lo : g_wc_lo;

    int tid  = threadIdx.x;
    int lane = tid & 31;
    int wid  = tid >> 5;
    int g = lane >> 2, t = lane & 3;
    int wm0 = (wid >> 1) << 5;
    int wn0 = (wid & 1) << 5;
    int m0 = blockIdx.y << 7, n0 = blockIdx.x << 6;

    int a_row  = tid >> 1;              // 0..127
    int a_half = (tid & 1) << 3;        // 0 or 8
    int b_row  = tid >> 2;              // 0..63
    int b_q    = (tid & 3) << 2;        // 0,4,8,12

    float acc[2][4][4] = {};

    for (int s = 0; s < 19; s++) {
        int k0p = s << 4;
        // A tile: each thread 2x uint4 per plane
        {
            size_t gb = (size_t)(m0 + a_row) * PAIRS + k0p + a_half;
            *(uint4*)&Ah[a_row * 20 + a_half]     = *(const uint4*)&Aph[gb];
            *(uint4*)&Ah[a_row * 20 + a_half + 4] = *(const uint4*)&Aph[gb + 4];
            *(uint4*)&Al[a_row * 20 + a_half]     = *(const uint4*)&Apl[gb];
            *(uint4*)&Al[a_row * 20 + a_half + 4] = *(const uint4*)&Apl[gb + 4];
        }
        // B tile: each thread 1 uint4 per plane
        {
            size_t gb = (size_t)(n0 + b_row) * PAIRS + k0p + b_q;
            *(uint4*)&Bh[b_row * 20 + b_q] = *(const uint4*)&Wph[gb];
            *(uint4*)&Bl[b_row * 20 + b_q] = *(const uint4*)&Wpl[gb];
        }
        __syncthreads();

        #pragma unroll
        for (int kk = 0; kk < 2; kk++) {
            int kp0 = (kk << 3) + t, kp1 = kp0 + 4;
            uint32_t bHf[4][2], bLf[4][2];
            #pragma unroll
            for (int ni = 0; ni < 4; ni++) {
                int n = wn0 + (ni << 3) + g;
                bHf[ni][0] = Bh[n * 20 + kp0]; bHf[ni][1] = Bh[n * 20 + kp1];
                bLf[ni][0] = Bl[n * 20 + kp0]; bLf[ni][1] = Bl[n * 20 + kp1];
            }
            #pragma unroll
            for (int mi = 0; mi < 2; mi++) {
                int r0m = wm0 + (mi << 4) + g;
                uint32_t aH[4] = { Ah[r0m * 20 + kp0], Ah[(r0m + 8) * 20 + kp0],
                                   Ah[r0m * 20 + kp1], Ah[(r0m + 8) * 20 + kp1] };
                uint32_t aL[4] = { Al[r0m * 20 + kp0], Al[(r0m + 8) * 20 + kp0],
                                   Al[r0m * 20 + kp1], Al[(r0m + 8) * 20 + kp1] };
                #pragma unroll
                for (int ni = 0; ni < 4; ni++) {
                    mma_bf16(acc[mi][ni], aL, bHf[ni]);
                    mma_bf16(acc[mi][ni], aH, bLf[ni]);
                    mma_bf16(acc[mi][ni], aH, bHf[ni]);
                }
            }
        }
        __syncthreads();
    }

    // epilogue: thread owns (o, o+1) even pairs; rows g / g+8
    #pragma unroll
    for (int mi = 0; mi < 2; mi++)
        #pragma unroll
        for (int rh = 0; rh < 2; rh++) {
            int m = m0 + wm0 + (mi << 4) + g + (rh << 3);
            int b = m >> 10, n = m & 1023;
            #pragma unroll
            for (int ni = 0; ni < 4; ni++) {
                int o = n0 + wn0 + (ni << 3) + 2 * t;     // even
                if (o >= NCOLS) continue;
                float v0 = acc[mi][ni][rh * 2 + 0] + bias[o];
                float v1 = acc[mi][ni][rh * 2 + 1] + bias[o + 1];
                if (!SCATTER) {
                    // tokens: o-pair == GEMM2 k-pair -> split in place
                    uint32_t hw, lw;
                    split_pair(v0, v1, hw, lw);
                    size_t tb = (size_t)m * PAIRS + (o >> 1);
                    g_ta_hi[tb] = hw;
                    g_ta_lo[tb] = lw;
                } else {
                    int sgrp = o / CDIM;
                    int cc   = o - sgrp * CDIM;           // even
                    int h    = cc / HD;
                    int d    = cc - h * HD;               // even
                    int bh   = b * NH + h;
                    if (sgrp < 2) {
                        uint32_t hw, lw;
                        split_pair(v0, v1, hw, lw);
                        size_t base = ((size_t)bh * NTOK + n) * 24 + (d >> 1);
                        if (sgrp == 0) { g_qp_hi[base] = hw; g_qp_lo[base] = lw; }
                        else           { g_kp_hi[base] = hw; g_kp_lo[base] = lw; }
                    } else {
                        #pragma unroll
                        for (int e = 0; e < 2; e++) {
                            float val = e ? v1 : v0;
                            uint16_t hb;
                            asm("cvt.rn.bf16.f32 %0, %1;" : "=h"(hb) : "f"(val));
                            float rv = val - __uint_as_float((uint32_t)hb << 16);
                            uint16_t lb;
                            asm("cvt.rn.bf16.f32 %0, %1;" : "=h"(lb) : "f"(rv));
                            size_t vo = ((size_t)bh * 48 + d + e) * NTOK + n;
                            g_vh16[vo] = hb; g_vl16[vo] = lb;
                        }
                    }
                }
            }
        }
}

// ---------------------------------------------------------------------------
// bf16 tensor-core flash attention (round 8, unchanged)
// ---------------------------------------------------------------------------
__global__ __launch_bounds__(256) void attn_k(float* __restrict__ out) {
    __shared__ uint32_t Qh[64 * 28];
    __shared__ uint32_t Ql[64 * 28];
    __shared__ uint32_t KPr[4608];
    __shared__ uint32_t Vh[48 * 36];
    __shared__ uint32_t Vl[48 * 36];
    __shared__ float smax[2][64];
    __shared__ float ssum[2][64];

    int tid  = threadIdx.x;
    int lane = tid & 31, w = tid >> 5;
    int g = lane >> 2, t = lane & 3;
    int wm    = (w & 3) << 4;
    int whalf = w >> 2;
    int ncol0 = whalf << 5;
    int dcol0 = whalf * 24;
    int bh = blockIdx.y;
    int r0 = blockIdx.x << 6;

    for (int idx = tid; idx < 64 * 24; idx += 256) {
        int r = idx / 24, p = idx - r * 24;
        size_t gb = ((size_t)bh * NTOK + r0 + r) * 24 + p;
        Qh[r * 28 + p] = g_qp_hi[gb];
        Ql[r * 28 + p] = g_qp_lo[gb];
    }

    float m0r = -1e30f, m1r = -1e30f, l0r = 0.f, l1r = 0.f;
    float o[3][4] = {};

    for (int c0 = 0; c0 < NTOK; c0 += 64) {
        for (int idx = tid; idx < 64 * 24; idx += 256) {
            int n = idx / 24, p = idx - n * 24;
            size_t gb = ((size_t)bh * NTOK + c0 + n) * 24 + p;
            KPr[n * 28 + p]        = g_kp_hi[gb];
            KPr[1792 + n * 28 + p] = g_kp_lo[gb];
        }
        for (int idx = tid; idx < 48 * 32; idx += 256) {
            int d = idx / 32, p = idx - d * 32;
            size_t gb = ((size_t)bh * 48 + d) * NTOK + c0 + 2 * p;
            Vh[d * 36 + p] = *(const uint32_t*)&g_vh16[gb];
            Vl[d * 36 + p] = *(const uint32_t*)&g_vl16[gb];
        }
        __syncthreads();

        float s[4][4] = {};
        #pragma unroll
        for (int kk = 0; kk < 3; kk++) {
            int kp0 = 8 * kk + t, kp1 = kp0 + 4;
            uint32_t aH[4] = { Qh[(wm + g) * 28 + kp0], Qh[(wm + 8 + g) * 28 + kp0],
                               Qh[(wm + g) * 28 + kp1], Qh[(wm + 8 + g) * 28 + kp1] };
            uint32_t aL[4] = { Ql[(wm + g) * 28 + kp0], Ql[(wm + 8 + g) * 28 + kp0],
                               Ql[(wm + g) * 28 + kp1], Ql[(wm + 8 + g) * 28 + kp1] };
            #pragma unroll
            for (int nb = 0; nb < 4; nb++) {
                int n = ncol0 + (nb << 3) + g;
                uint32_t bH[2] = { KPr[n * 28 + kp0], KPr[n * 28 + kp1] };
                uint32_t bL[2] = { KPr[1792 + n * 28 + kp0], KPr[1792 + n * 28 + kp1] };
                mma_bf16(s[nb], aL, bH);
                mma_bf16(s[nb], aH, bL);
                mma_bf16(s[nb], aH, bH);
            }
        }

        float pm0 = -1e30f, pm1 = -1e30f;
        #pragma unroll
        for (int nb = 0; nb < 4; nb++) {
            s[nb][0] *= ATTN_SCALE; s[nb][1] *= ATTN_SCALE;
            s[nb][2] *= ATTN_SCALE; s[nb][3] *= ATTN_SCALE;
            pm0 = fmaxf(pm0, fmaxf(s[nb][0], s[nb][1]));
            pm1 = fmaxf(pm1, fmaxf(s[nb][2], s[nb][3]));
        }
        pm0 = fmaxf(pm0, __shfl_xor_sync(0xffffffffu, pm0, 1));
        pm0 = fmaxf(pm0, __shfl_xor_sync(0xffffffffu, pm0, 2));
        pm1 = fmaxf(pm1, __shfl_xor_sync(0xffffffffu, pm1, 1));
        pm1 = fmaxf(pm1, __shfl_xor_sync(0xffffffffu, pm1, 2));
        if (t == 0) { smax[whalf][wm + g] = pm0; smax[whalf][wm + 8 + g] = pm1; }
        __syncthreads();

        float mn0 = fmaxf(m0r, fmaxf(smax[0][wm + g],     smax[1][wm + g]));
        float mn1 = fmaxf(m1r, fmaxf(smax[0][wm + 8 + g], smax[1][wm + 8 + g]));
        float al0 = __expf(m0r - mn0), al1 = __expf(m1r - mn1);
        m0r = mn0; m1r = mn1;

        float ps0 = 0.f, ps1 = 0.f;
        #pragma unroll
        for (int nb = 0; nb < 4; nb++) {
            s[nb][0] = __expf(s[nb][0] - mn0); s[nb][1] = __expf(s[nb][1] - mn0);
            s[nb][2] = __expf(s[nb][2] - mn1); s[nb][3] = __expf(s[nb][3] - mn1);
            ps0 += s[nb][0] + s[nb][1];
            ps1 += s[nb][2] + s[nb][3];
        }
        ps0 += __shfl_xor_sync(0xffffffffu, ps0, 1);
        ps0 += __shfl_xor_sync(0xffffffffu, ps0, 2);
        ps1 += __shfl_xor_sync(0xffffffffu, ps1, 1);
        ps1 += __shfl_xor_sync(0xffffffffu, ps1, 2);
        if (t == 0) { ssum[whalf][wm + g] = ps0; ssum[whalf][wm + 8 + g] = ps1; }

        #pragma unroll
        for (int nb = 0; nb < 4; nb++) {
            int pcol = (ncol0 >> 1) + 4 * nb + t;
            uint32_t h0, l0, h1, l1;
            split_pair(s[nb][0], s[nb][1], h0, l0);
            split_pair(s[nb][2], s[nb][3], h1, l1);
            KPr[(wm + g) * 36 + pcol]            = h0;
            KPr[2304 + (wm + g) * 36 + pcol]     = l0;
            KPr[(wm + 8 + g) * 36 + pcol]        = h1;
            KPr[2304 + (wm + 8 + g) * 36 + pcol] = l1;
        }
        __syncthreads();

        l0r = l0r * al0 + ssum[0][wm + g]     + ssum[1][wm + g];
        l1r = l1r * al1 + ssum[0][wm + 8 + g] + ssum[1][wm + 8 + g];
        #pragma unroll
        for (int f = 0; f < 3; f++) {
            o[f][0] *= al0; o[f][1] *= al0; o[f][2] *= al1; o[f][3] *= al1;
        }

        #pragma unroll
        for (int kk = 0; kk < 4; kk++) {
            int kp0 = 8 * kk + t, kp1 = kp0 + 4;
            uint32_t aH[4] = { KPr[(wm + g) * 36 + kp0], KPr[(wm + 8 + g) * 36 + kp0],
                               KPr[(wm + g) * 36 + kp1], KPr[(wm + 8 + g) * 36 + kp1] };
            uint32_t aL[4] = { KPr[2304 + (wm + g) * 36 + kp0], KPr[2304 + (wm + 8 + g) * 36 + kp0],
                               KPr[2304 + (wm + g) * 36 + kp1], KPr[2304 + (wm + 8 + g) * 36 + kp1] };
            #pragma unroll
            for (int nb = 0; nb < 3; nb++) {
                int dd = dcol0 + (nb << 3) + g;
                uint32_t bH[2] = { Vh[dd * 36 + kp0], Vh[dd * 36 + kp1] };
                uint32_t bL[2] = { Vl[dd * 36 + kp0], Vl[dd * 36 + kp1] };
                mma_bf16(o[nb], aL, bH);
                mma_bf16(o[nb], aH, bL);
                mma_bf16(o[nb], aH, bH);
            }
        }
        __syncthreads();
    }

    int b = bh / NH, h = bh - b * NH;
    float inv0 = 1.f / l0r, inv1 = 1.f / l1r;
    size_t row0 = (size_t)(b * NTOK + r0 + wm + g) * CDIM + h * HD;
    size_t row1 = (size_t)(b * NTOK + r0 + wm + 8 + g) * CDIM + h * HD;
    #pragma unroll
    for (int nb = 0; nb < 3; nb++) {
        int d = dcol0 + (nb << 3) + (t << 1);
        if (d < HD)     out[row0 + d]     = o[nb][0] * inv0;
        if (d + 1 < HD) out[row0 + d + 1] = o[nb][1] * inv0;
        if (d < HD)     out[row1 + d]     = o[nb][2] * inv1;
        if (d + 1 < HD) out[row1 + d + 1] = o[nb][3] * inv1;
    }
}

// ---------------------------------------------------------------------------
extern "C" void kernel_launch(void* const* d_in, const int* in_sizes, int n_in,
                              void* d_out, int out_size) {
    const float* x      = (const float*)d_in[0];
    const float* conv_w = (const float*)d_in[1];
    const float* conv_b = (const float*)d_in[2];
    const float* qkv_w  = (const float*)d_in[3];
    const float* qkv_b  = (const float*)d_in[4];
    float* out = (float*)d_out;

    patch_split_k<<<(MTOT * 294 + 255) / 256, 256>>>(x);
    weight_split_k<<<(CDIM * 294 + 255) / 256, 256>>>(conv_w, CDIM, 0);
    weight_split_k<<<(QKVN * 294 + 255) / 256, 256>>>(qkv_w, QKVN, 1);
    gemm_bf16_k<CDIM, false><<<dim3(NPAD1 / 64, MTOT / 128), 256>>>(conv_b);
    gemm_bf16_k<QKVN, true ><<<dim3(NPAD2 / 64, MTOT / 128), 256>>>(qkv_b);
    attn_k<<<dim3(NTOK / 64, B_ * NH), 256>>>(out);
}